// round 16
// baseline (speedup 1.0000x reference)
#include <cuda_runtime.h>
#include <cuda_fp16.h>
#include <mma.h>
#include <cstdint>

using namespace nvcuda;

// Problem constants
#define BSZ   64
#define PP    512
#define DWM   1024
#define WIN   128
#define MROWS (BSZ * PP)   // 32768
#define TQ    8

// 16-byte vector of 8 halves for single-STG.128 stores
struct __align__(16) h2x4 { __half2 a, b, c, d; };

// ---------------------------------------------------------------------------
// Scratch (device globals — no allocation allowed)
// ---------------------------------------------------------------------------
__device__ __half g_q [(size_t)MROWS * DWM];     // Q in half (GEMM epilogue out)
__device__ __half g_k [(size_t)MROWS * DWM];
__device__ __half g_v [(size_t)MROWS * DWM];
__device__ __half g_o [(size_t)MROWS * DWM];     // attention out (half)
__device__ __half g_xh[(size_t)MROWS * DWM];     // x in half
__device__ __half g_w [(size_t)4 * 1024 * 1024]; // 4 weights [K,N], half
__device__ float  g_bias[4 * 1024];
__device__ int    g_start[BSZ * PP];

// ---------------------------------------------------------------------------
// Helpers (portable PTX only — compute_103 virtual arch, no tcgen05)
// ---------------------------------------------------------------------------
__device__ __forceinline__ uint32_t smem_u32(const void* p) {
    uint32_t a;
    asm("{ .reg .u64 t; cvta.to.shared.u64 t, %1; cvt.u32.u64 %0, t; }" : "=r"(a) : "l"(p));
    return a;
}
#define CP16(d, s)  asm volatile("cp.async.cg.shared.global [%0], [%1], 16;" :: "r"(d), "l"(s) : "memory")
#define CP_COMMIT() asm volatile("cp.async.commit_group;" ::: "memory")
#define CP_WAIT1()  asm volatile("cp.async.wait_group 1;" ::: "memory")

// ---------------------------------------------------------------------------
// Prep: reset-mask dtype probe + window start indices + bias copy
// ---------------------------------------------------------------------------
__global__ void prep_kernel(const unsigned char* __restrict__ reset_raw,
                            const float* __restrict__ bq, const float* __restrict__ bk,
                            const float* __restrict__ bv, const float* __restrict__ bo)
{
    __shared__ int s_ni, s_nf, s_any;
    if (threadIdx.x == 0) { s_ni = 0; s_nf = 0; s_any = 0; }
    __syncthreads();
    const unsigned int* w32 = (const unsigned int*)reset_raw;
    int ni = 0, nf = 0, any = 0;
    for (int i = threadIdx.x; i < 8192; i += blockDim.x) {   // 32768 bytes, safe all dtypes
        unsigned int v = w32[i];
        if (v != 0u) {
            any = 1;
            if (v != 1u)          ni = 1;
            if (v != 0x3f800000u) nf = 1;
        }
    }
    if (ni)  atomicOr(&s_ni, 1);
    if (nf)  atomicOr(&s_nf, 1);
    if (any) atomicOr(&s_any, 1);
    __syncthreads();
    int mode;
    if (!s_any)      mode = -1;
    else if (!s_ni)  mode = 1;
    else if (!s_nf)  mode = 2;
    else             mode = 0;

    for (int b = threadIdx.x; b < BSZ; b += blockDim.x) {
        int r = 0;
        for (int t = 0; t < PP; t++) {
            int idx = b * PP + t;
            bool reset = false;
            if (mode == 0)      reset = (reset_raw[idx] != 0);
            else if (mode > 0)  reset = (w32[idx] != 0u);
            if (reset) r = t;
            int s = t - (WIN - 1);
            if (s < r) s = r;
            if (s < 0) s = 0;
            g_start[idx] = s;
        }
    }
    for (int i = threadIdx.x; i < 1024; i += blockDim.x) {
        g_bias[i]        = bq[i];
        g_bias[1024 + i] = bk[i];
        g_bias[2048 + i] = bv[i];
        g_bias[3072 + i] = bo[i];
    }
}

// ---------------------------------------------------------------------------
// Convert x / weights to half (one RN rounding)
// ---------------------------------------------------------------------------
__global__ void conv_x_kernel(const float4* __restrict__ x)
{
    size_t i = (size_t)blockIdx.x * blockDim.x + threadIdx.x;
    float4 v = x[i];
    __half2 p0 = __floats2half2_rn(v.x, v.y);
    __half2 p1 = __floats2half2_rn(v.z, v.w);
    __half2* dst = reinterpret_cast<__half2*>(g_xh) + 2 * i;
    dst[0] = p0; dst[1] = p1;
}

__global__ void conv_w_kernel(const float4* __restrict__ W0, const float4* __restrict__ W1,
                              const float4* __restrict__ W2, const float4* __restrict__ W3)
{
    const float4* W = (blockIdx.y == 0) ? W0 : (blockIdx.y == 1) ? W1
                    : (blockIdx.y == 2) ? W2 : W3;
    size_t i = (size_t)blockIdx.x * blockDim.x + threadIdx.x;   // 0..262143
    float4 v = W[i];
    __half2 p0 = __floats2half2_rn(v.x, v.y);
    __half2 p1 = __floats2half2_rn(v.z, v.w);
    __half2* dst = reinterpret_cast<__half2*>(g_w) + (size_t)blockIdx.y * 524288 + 2 * i;
    dst[0] = p0; dst[1] = p1;
}

// ---------------------------------------------------------------------------
// Pipelined FP16 WMMA GEMM (proven config — measured 675us QKV / 225us proj;
// smem-crossbar/tensor co-bound at its local optimum for this ISA — frozen).
// Block 128x128, K-tile 32, 3-stage cp.async ring, 8 warps 4Mx2N,
// warp tile 32x64, 2 CTAs/SM.
//   asel:  0 -> A = g_xh, 1 -> A = g_o
//   wbase: 0 for fused QKV (half out to g_q/g_k/g_v), 3 for output proj (f32)
// ---------------------------------------------------------------------------
#define GBK   32
#define LDAh  40            // halves: 32 + 8 pad (80B rows)
#define LDBh  136           // halves: 128 + 8 pad (272B rows)
#define STG_AH    (128 * LDAh)                    // 5120 halves
#define STG_B_OFF (STG_AH * 2)                    // 10240 bytes
#define STG_BYTES (STG_B_OFF + GBK * LDBh * 2)    // 18944 bytes
#define GSMEM (3 * STG_BYTES)                     // 56832 bytes (2 CTAs/SM)

__global__ __launch_bounds__(256, 2)
void gemm_fp16_kernel(float* __restrict__ Cext, int asel, int wbase)
{
    extern __shared__ char smemraw[];
    const uint32_t sb = smem_u32(smemraw);
    const int tid = threadIdx.x, warp = tid >> 5, lane = tid & 31;
    const int w  = wbase + (blockIdx.x >> 3);
    const int bn = blockIdx.x & 7;
    const int bm = blockIdx.y;
    const int wm = warp & 3;      // 4 warps along M
    const int wn = warp >> 2;     // 2 warps along N

    const __half* A  = asel ? g_o : g_xh;
    const __half* Bw = g_w + (size_t)w * 1048576 + bn * 128;
    __half* Ch = (w == 0) ? g_q : (w == 1) ? g_k : g_v;   // used when w<3
    const float* bias = g_bias + w * 1024;

    const __half* Ab = A + (size_t)bm * 128 * 1024;

    // Per-thread cp.async plan: 2 A-chunks + 2 B-chunks of 16B (8 halves)
    const __half* asrc[2]; const __half* bsrc[2];
    uint32_t aoff[2], boff[2];
#pragma unroll
    for (int i = 0; i < 2; i++) {
        int idx = tid + i * 256;   // 0..511
        {   // A tile: 128 rows x 32 halves (4 chunks/row)
            int r = idx >> 2, c = idx & 3;
            asrc[i] = Ab + (size_t)r * 1024 + c * 8;
            aoff[i] = (uint32_t)(r * LDAh + c * 8) * 2;
        }
        {   // B tile: 32 rows (K) x 128 halves (16 chunks/row)
            int r = idx >> 4, c = idx & 15;
            bsrc[i] = Bw + (size_t)r * 1024 + c * 8;
            boff[i] = STG_B_OFF + (uint32_t)(r * LDBh + c * 8) * 2;
        }
    }

    wmma::fragment<wmma::accumulator, 16, 16, 16, float> acc[2][4];
#pragma unroll
    for (int mi = 0; mi < 2; mi++)
#pragma unroll
        for (int ni = 0; ni < 4; ni++)
            wmma::fill_fragment(acc[mi][ni], 0.0f);

    // Prologue: tiles 0,1 -> stages 0,1
#pragma unroll
    for (int t = 0; t < 2; t++) {
        uint32_t st = sb + t * STG_BYTES;
#pragma unroll
        for (int i = 0; i < 2; i++) CP16(st + aoff[i], asrc[i] + t * 32);
#pragma unroll
        for (int i = 0; i < 2; i++) CP16(st + boff[i], bsrc[i] + (size_t)t * 32 * 1024);
        CP_COMMIT();
    }

    int s = 0;
    for (int t = 0; t < 32; t++) {
        CP_WAIT1();            // tile t landed (this thread)
        __syncthreads();       // ...for all threads; licenses overwriting stage
                               // (t+2)%3 == (t-1)%3 (consumed last iteration)

        const __half* sA  = (const __half*)(smemraw + s * STG_BYTES);
        const __half* sBt = (const __half*)(smemraw + s * STG_BYTES + STG_B_OFF);
#pragma unroll
        for (int kk = 0; kk < GBK; kk += 16) {
            wmma::fragment<wmma::matrix_a, 16, 16, 16, __half, wmma::row_major> af[2];
            wmma::fragment<wmma::matrix_b, 16, 16, 16, __half, wmma::row_major> bf[4];
#pragma unroll
            for (int mi = 0; mi < 2; mi++)
                wmma::load_matrix_sync(af[mi], sA + (wm * 32 + mi * 16) * LDAh + kk, LDAh);
#pragma unroll
            for (int ni = 0; ni < 4; ni++)
                wmma::load_matrix_sync(bf[ni], sBt + kk * LDBh + wn * 64 + ni * 16, LDBh);
#pragma unroll
            for (int mi = 0; mi < 2; mi++)
#pragma unroll
                for (int ni = 0; ni < 4; ni++)
                    wmma::mma_sync(acc[mi][ni], af[mi], bf[ni], acc[mi][ni]);
        }

        // Prefetch tile t+2 into stage (t+2)%3
        const int tp = t + 2;
        if (tp < 32) {
            int sp = s + 2; if (sp >= 3) sp -= 3;
            uint32_t st = sb + sp * STG_BYTES;
#pragma unroll
            for (int i = 0; i < 2; i++) CP16(st + aoff[i], asrc[i] + tp * 32);
#pragma unroll
            for (int i = 0; i < 2; i++) CP16(st + boff[i], bsrc[i] + (size_t)tp * 32 * 1024);
        }
        CP_COMMIT();

        if (++s == 3) s = 0;
    }
    __syncthreads();   // protect smem scratch reuse below

    // Epilogue: per-warp 16x20 scratch roundtrip (f32), bias add,
    // half (internal QKV) or float (final y) vectorized stores.
    float* myC = (float*)smemraw + warp * 16 * 20;
    const int r  = lane >> 1;
    const int ch = (lane & 1) * 8;
    const bool outHalf = (w < 3);
#pragma unroll
    for (int mi = 0; mi < 2; mi++)
#pragma unroll
        for (int ni = 0; ni < 4; ni++) {
            wmma::store_matrix_sync(myC, acc[mi][ni], 20, wmma::mem_row_major);
            __syncwarp();
            int gm = bm * 128 + wm * 32 + mi * 16 + r;
            int gn = bn * 128 + wn * 64 + ni * 16 + ch;
            float c0 = myC[r * 20 + ch + 0] + bias[gn + 0];
            float c1 = myC[r * 20 + ch + 1] + bias[gn + 1];
            float c2 = myC[r * 20 + ch + 2] + bias[gn + 2];
            float c3 = myC[r * 20 + ch + 3] + bias[gn + 3];
            float c4 = myC[r * 20 + ch + 4] + bias[gn + 4];
            float c5 = myC[r * 20 + ch + 5] + bias[gn + 5];
            float c6 = myC[r * 20 + ch + 6] + bias[gn + 6];
            float c7 = myC[r * 20 + ch + 7] + bias[gn + 7];
            if (outHalf) {
                h2x4 pk;
                pk.a = __floats2half2_rn(c0, c1);
                pk.b = __floats2half2_rn(c2, c3);
                pk.c = __floats2half2_rn(c4, c5);
                pk.d = __floats2half2_rn(c6, c7);
                *(h2x4*)(Ch + (size_t)gm * 1024 + gn) = pk;
            } else {
                *(float4*)(Cext + (size_t)gm * 1024 + gn)     = make_float4(c0, c1, c2, c3);
                *(float4*)(Cext + (size_t)gm * 1024 + gn + 4) = make_float4(c4, c5, c6, c7);
            }
            __syncwarp();
        }
}

// ---------------------------------------------------------------------------
// Sliding-window attention, max-free softmax, j-loop UNROLLED x4.
// 128-thread blocks (4 warps = 8 heads), gridDim.z = 2 splits the 16 heads:
// keeps regs*threads low enough for 3 blocks (12 warps)/SM while per-warp
// MLP rises to 16 loads in flight and 4 independent shfl trees give ILP 4
// on the reduction chain. Updates applied j..j+3 sequentially -> accumulation
// order bitwise-identical to the unrolled-by-1 version.
// Warp w owns heads z*8 + 2w, 2w+1; 16 lanes/head, 4 head-dims/lane.
// ---------------------------------------------------------------------------
__global__ __launch_bounds__(128)
void attn_kernel()
{
    const int b    = blockIdx.x;
    const int tb   = blockIdx.y * TQ;
    const int warp = threadIdx.x >> 5;
    const int lane = threadIdx.x & 31;
    const int h    = blockIdx.z * 8 + warp * 2 + (lane >> 4);
    const int sub  = lane & 15;
    const int d0   = h * 64 + sub * 4;

    const __half* qb = g_q + (size_t)b * PP * DWM;
    const __half* kb = g_k + (size_t)b * PP * DWM;
    const __half* vb = g_v + (size_t)b * PP * DWM;
    __half*       ob = g_o + (size_t)b * PP * DWM;

    float4 q4[TQ], acc[TQ];
    float  l[TQ];
    int    st[TQ];
#pragma unroll
    for (int i = 0; i < TQ; i++) {
        int t = tb + i;
        const __half2* qp = (const __half2*)(qb + (size_t)t * DWM + d0);
        float2 f0 = __half22float2(qp[0]);
        float2 f1 = __half22float2(qp[1]);
        // pre-scale by 1/sqrt(64)=0.125 (exact) -> drops one FMUL per (i,j)
        q4[i]  = make_float4(f0.x * 0.125f, f0.y * 0.125f,
                             f1.x * 0.125f, f1.y * 0.125f);
        st[i]  = g_start[b * PP + t];
        l[i]   = 0.0f;
        acc[i] = make_float4(0.f, 0.f, 0.f, 0.f);
    }

    const int jmin = st[0];            // start index monotone in t
    const int jmax = tb + TQ - 1;

    int j = jmin;
    for (; j + 3 <= jmax; j += 4) {
        // ---- load 4 K rows + 4 V rows up front (16 independent LDG.64) ----
        float4 k4[4], v4[4];
#pragma unroll
        for (int u = 0; u < 4; u++) {
            const __half2* kp = (const __half2*)(kb + (size_t)(j + u) * DWM + d0);
            const __half2* vp = (const __half2*)(vb + (size_t)(j + u) * DWM + d0);
            __half2 ka = kp[0], kbh = kp[1], va = vp[0], vbh = vp[1];
            float2 kf0 = __half22float2(ka),  kf1 = __half22float2(kbh);
            float2 vf0 = __half22float2(va),  vf1 = __half22float2(vbh);
            k4[u] = make_float4(kf0.x, kf0.y, kf1.x, kf1.y);
            v4[u] = make_float4(vf0.x, vf0.y, vf1.x, vf1.y);
        }

        // ---- 4 independent dot sets ----
        float sc[4][TQ];
#pragma unroll
        for (int u = 0; u < 4; u++)
#pragma unroll
            for (int i = 0; i < TQ; i++)
                sc[u][i] = q4[i].x * k4[u].x + q4[i].y * k4[u].y
                         + q4[i].z * k4[u].z + q4[i].w * k4[u].w;

        // ---- 4 interleaved reduction trees (ILP 4 on the shfl chain) ----
#pragma unroll
        for (int off = 8; off >= 1; off >>= 1)
#pragma unroll
            for (int i = 0; i < TQ; i++)
#pragma unroll
                for (int u = 0; u < 4; u++)
                    sc[u][i] += __shfl_xor_sync(0xffffffffu, sc[u][i], off, 16);

        // ---- updates j, j+1, j+2, j+3 in order (bitwise-identical) ----
#pragma unroll
        for (int u = 0; u < 4; u++) {
            int ju = j + u;
#pragma unroll
            for (int i = 0; i < TQ; i++) {
                int t = tb + i;
                if (ju >= st[i] && ju <= t) {
                    float wt = __expf(sc[u][i]);
                    l[i] += wt;
                    acc[i].x += wt * v4[u].x;
                    acc[i].y += wt * v4[u].y;
                    acc[i].z += wt * v4[u].z;
                    acc[i].w += wt * v4[u].w;
                }
            }
        }
    }

    // ---- tail: 0..3 remaining j's, one at a time ----
    for (; j <= jmax; j++) {
        const __half2* kp = (const __half2*)(kb + (size_t)j * DWM + d0);
        const __half2* vp = (const __half2*)(vb + (size_t)j * DWM + d0);
        float2 k0 = __half22float2(kp[0]), k1 = __half22float2(kp[1]);
        float2 v0 = __half22float2(vp[0]), v1 = __half22float2(vp[1]);
        float4 k4 = make_float4(k0.x, k0.y, k1.x, k1.y);
        float4 v4 = make_float4(v0.x, v0.y, v1.x, v1.y);
        float s[TQ];
#pragma unroll
        for (int i = 0; i < TQ; i++)
            s[i] = q4[i].x * k4.x + q4[i].y * k4.y + q4[i].z * k4.z + q4[i].w * k4.w;
#pragma unroll
        for (int off = 8; off >= 1; off >>= 1)
#pragma unroll
            for (int i = 0; i < TQ; i++)
                s[i] += __shfl_xor_sync(0xffffffffu, s[i], off, 16);
#pragma unroll
        for (int i = 0; i < TQ; i++) {
            int t = tb + i;
            if (j >= st[i] && j <= t) {
                float wt = __expf(s[i]);
                l[i] += wt;
                acc[i].x += wt * v4.x;
                acc[i].y += wt * v4.y;
                acc[i].z += wt * v4.z;
                acc[i].w += wt * v4.w;
            }
        }
    }

#pragma unroll
    for (int i = 0; i < TQ; i++) {
        float inv = 1.0f / l[i];
        __half2 p0 = __floats2half2_rn(acc[i].x * inv, acc[i].y * inv);
        __half2 p1 = __floats2half2_rn(acc[i].z * inv, acc[i].w * inv);
        __half2* dst = (__half2*)(ob + (size_t)(tb + i) * DWM + d0);
        dst[0] = p0; dst[1] = p1;
    }
}

// ---------------------------------------------------------------------------
// Launch
// ---------------------------------------------------------------------------
extern "C" void kernel_launch(void* const* d_in, const int* in_sizes, int n_in,
                              void* d_out, int out_size)
{
    const float*         x  = (const float*)d_in[0];
    const unsigned char* rs = (const unsigned char*)d_in[1];
    const float* Wq = (const float*)d_in[2];
    const float* bq = (const float*)d_in[3];
    const float* Wk = (const float*)d_in[4];
    const float* bk = (const float*)d_in[5];
    const float* Wv = (const float*)d_in[6];
    const float* bv = (const float*)d_in[7];
    const float* Wo = (const float*)d_in[8];
    const float* bo = (const float*)d_in[9];
    float* y = (float*)d_out;

    cudaFuncSetAttribute(gemm_fp16_kernel,
                         cudaFuncAttributeMaxDynamicSharedMemorySize, GSMEM);

    prep_kernel<<<1, 256>>>(rs, bq, bk, bv, bo);
    conv_x_kernel<<<32768, 256>>>((const float4*)x);
    conv_w_kernel<<<dim3(1024, 4), 256>>>((const float4*)Wq, (const float4*)Wk,
                                          (const float4*)Wv, (const float4*)Wo);

    // Fused Q,K,V projections: grid.x = 3 weights * 8 bn, grid.y = 32768/128
    gemm_fp16_kernel<<<dim3(24, 256), 256, GSMEM>>>(nullptr, 0, 0);

    // Attention: 128-thread blocks, heads split across grid.z
    attn_kernel<<<dim3(BSZ, PP / TQ, 2), 128>>>();

    // y = attn_out @ Wo + bo (f32 out)
    gemm_fp16_kernel<<<dim3(8, 256), 256, GSMEM>>>(y, 1, 3);
}

// round 17
// speedup vs baseline: 1.2313x; 1.2313x over previous
#include <cuda_runtime.h>
#include <cuda_fp16.h>
#include <mma.h>
#include <cstdint>

using namespace nvcuda;

// Problem constants
#define BSZ   64
#define PP    512
#define DWM   1024
#define WIN   128
#define MROWS (BSZ * PP)   // 32768
#define ATQ   16           // queries per attention tile (wmma M)

// 16-byte vector of 8 halves for single-STG.128 stores
struct __align__(16) h2x4 { __half2 a, b, c, d; };

// ---------------------------------------------------------------------------
// Scratch (device globals — no allocation allowed). K/V padded by 16 rows so
// the attention's last 16-wide chunk may read past row 511 of batch 63
// (values are zero-filled at module load and masked to weight 0 anyway).
// ---------------------------------------------------------------------------
__device__ __half g_q [(size_t)MROWS * DWM];
__device__ __half g_k [(size_t)(MROWS + 16) * DWM];
__device__ __half g_v [(size_t)(MROWS + 16) * DWM];
__device__ __half g_o [(size_t)MROWS * DWM];     // attention out (half)
__device__ __half g_xh[(size_t)MROWS * DWM];     // x in half
__device__ __half g_w [(size_t)4 * 1024 * 1024]; // 4 weights [K,N], half
__device__ float  g_bias[4 * 1024];
__device__ int    g_start[BSZ * PP];

// ---------------------------------------------------------------------------
// Helpers (portable PTX only — compute_103 virtual arch, no tcgen05)
// ---------------------------------------------------------------------------
__device__ __forceinline__ uint32_t smem_u32(const void* p) {
    uint32_t a;
    asm("{ .reg .u64 t; cvta.to.shared.u64 t, %1; cvt.u32.u64 %0, t; }" : "=r"(a) : "l"(p));
    return a;
}
#define CP16(d, s)  asm volatile("cp.async.cg.shared.global [%0], [%1], 16;" :: "r"(d), "l"(s) : "memory")
#define CP_COMMIT() asm volatile("cp.async.commit_group;" ::: "memory")
#define CP_WAIT1()  asm volatile("cp.async.wait_group 1;" ::: "memory")

// ---------------------------------------------------------------------------
// Prep: reset-mask dtype probe + window start indices + bias copy
// ---------------------------------------------------------------------------
__global__ void prep_kernel(const unsigned char* __restrict__ reset_raw,
                            const float* __restrict__ bq, const float* __restrict__ bk,
                            const float* __restrict__ bv, const float* __restrict__ bo)
{
    __shared__ int s_ni, s_nf, s_any;
    if (threadIdx.x == 0) { s_ni = 0; s_nf = 0; s_any = 0; }
    __syncthreads();
    const unsigned int* w32 = (const unsigned int*)reset_raw;
    int ni = 0, nf = 0, any = 0;
    for (int i = threadIdx.x; i < 8192; i += blockDim.x) {   // 32768 bytes, safe all dtypes
        unsigned int v = w32[i];
        if (v != 0u) {
            any = 1;
            if (v != 1u)          ni = 1;
            if (v != 0x3f800000u) nf = 1;
        }
    }
    if (ni)  atomicOr(&s_ni, 1);
    if (nf)  atomicOr(&s_nf, 1);
    if (any) atomicOr(&s_any, 1);
    __syncthreads();
    int mode;
    if (!s_any)      mode = -1;
    else if (!s_ni)  mode = 1;
    else if (!s_nf)  mode = 2;
    else             mode = 0;

    for (int b = threadIdx.x; b < BSZ; b += blockDim.x) {
        int r = 0;
        for (int t = 0; t < PP; t++) {
            int idx = b * PP + t;
            bool reset = false;
            if (mode == 0)      reset = (reset_raw[idx] != 0);
            else if (mode > 0)  reset = (w32[idx] != 0u);
            if (reset) r = t;
            int s = t - (WIN - 1);
            if (s < r) s = r;
            if (s < 0) s = 0;
            g_start[idx] = s;
        }
    }
    for (int i = threadIdx.x; i < 1024; i += blockDim.x) {
        g_bias[i]        = bq[i];
        g_bias[1024 + i] = bk[i];
        g_bias[2048 + i] = bv[i];
        g_bias[3072 + i] = bo[i];
    }
}

// ---------------------------------------------------------------------------
// Convert x / weights to half (one RN rounding)
// ---------------------------------------------------------------------------
__global__ void conv_x_kernel(const float4* __restrict__ x)
{
    size_t i = (size_t)blockIdx.x * blockDim.x + threadIdx.x;
    float4 v = x[i];
    __half2 p0 = __floats2half2_rn(v.x, v.y);
    __half2 p1 = __floats2half2_rn(v.z, v.w);
    __half2* dst = reinterpret_cast<__half2*>(g_xh) + 2 * i;
    dst[0] = p0; dst[1] = p1;
}

__global__ void conv_w_kernel(const float4* __restrict__ W0, const float4* __restrict__ W1,
                              const float4* __restrict__ W2, const float4* __restrict__ W3)
{
    const float4* W = (blockIdx.y == 0) ? W0 : (blockIdx.y == 1) ? W1
                    : (blockIdx.y == 2) ? W2 : W3;
    size_t i = (size_t)blockIdx.x * blockDim.x + threadIdx.x;   // 0..262143
    float4 v = W[i];
    __half2 p0 = __floats2half2_rn(v.x, v.y);
    __half2 p1 = __floats2half2_rn(v.z, v.w);
    __half2* dst = reinterpret_cast<__half2*>(g_w) + (size_t)blockIdx.y * 524288 + 2 * i;
    dst[0] = p0; dst[1] = p1;
}

// ---------------------------------------------------------------------------
// Pipelined FP16 WMMA GEMM (proven config — measured 675us QKV / 225us proj;
// smem-crossbar/tensor co-bound at its local optimum for this ISA — frozen).
// Block 128x128, K-tile 32, 3-stage cp.async ring, 8 warps 4Mx2N,
// warp tile 32x64, 2 CTAs/SM.
//   asel:  0 -> A = g_xh, 1 -> A = g_o
//   wbase: 0 for fused QKV (half out to g_q/g_k/g_v), 3 for output proj (f32)
// ---------------------------------------------------------------------------
#define GBK   32
#define LDAh  40            // halves: 32 + 8 pad (80B rows)
#define LDBh  136           // halves: 128 + 8 pad (272B rows)
#define STG_AH    (128 * LDAh)                    // 5120 halves
#define STG_B_OFF (STG_AH * 2)                    // 10240 bytes
#define STG_BYTES (STG_B_OFF + GBK * LDBh * 2)    // 18944 bytes
#define GSMEM (3 * STG_BYTES)                     // 56832 bytes (2 CTAs/SM)

__global__ __launch_bounds__(256, 2)
void gemm_fp16_kernel(float* __restrict__ Cext, int asel, int wbase)
{
    extern __shared__ char smemraw[];
    const uint32_t sb = smem_u32(smemraw);
    const int tid = threadIdx.x, warp = tid >> 5, lane = tid & 31;
    const int w  = wbase + (blockIdx.x >> 3);
    const int bn = blockIdx.x & 7;
    const int bm = blockIdx.y;
    const int wm = warp & 3;      // 4 warps along M
    const int wn = warp >> 2;     // 2 warps along N

    const __half* A  = asel ? g_o : g_xh;
    const __half* Bw = g_w + (size_t)w * 1048576 + bn * 128;
    __half* Ch = (w == 0) ? g_q : (w == 1) ? g_k : g_v;   // used when w<3
    const float* bias = g_bias + w * 1024;

    const __half* Ab = A + (size_t)bm * 128 * 1024;

    // Per-thread cp.async plan: 2 A-chunks + 2 B-chunks of 16B (8 halves)
    const __half* asrc[2]; const __half* bsrc[2];
    uint32_t aoff[2], boff[2];
#pragma unroll
    for (int i = 0; i < 2; i++) {
        int idx = tid + i * 256;   // 0..511
        {   // A tile: 128 rows x 32 halves (4 chunks/row)
            int r = idx >> 2, c = idx & 3;
            asrc[i] = Ab + (size_t)r * 1024 + c * 8;
            aoff[i] = (uint32_t)(r * LDAh + c * 8) * 2;
        }
        {   // B tile: 32 rows (K) x 128 halves (16 chunks/row)
            int r = idx >> 4, c = idx & 15;
            bsrc[i] = Bw + (size_t)r * 1024 + c * 8;
            boff[i] = STG_B_OFF + (uint32_t)(r * LDBh + c * 8) * 2;
        }
    }

    wmma::fragment<wmma::accumulator, 16, 16, 16, float> acc[2][4];
#pragma unroll
    for (int mi = 0; mi < 2; mi++)
#pragma unroll
        for (int ni = 0; ni < 4; ni++)
            wmma::fill_fragment(acc[mi][ni], 0.0f);

    // Prologue: tiles 0,1 -> stages 0,1
#pragma unroll
    for (int t = 0; t < 2; t++) {
        uint32_t st = sb + t * STG_BYTES;
#pragma unroll
        for (int i = 0; i < 2; i++) CP16(st + aoff[i], asrc[i] + t * 32);
#pragma unroll
        for (int i = 0; i < 2; i++) CP16(st + boff[i], bsrc[i] + (size_t)t * 32 * 1024);
        CP_COMMIT();
    }

    int s = 0;
    for (int t = 0; t < 32; t++) {
        CP_WAIT1();            // tile t landed (this thread)
        __syncthreads();       // ...for all threads; licenses overwriting stage
                               // (t+2)%3 == (t-1)%3 (consumed last iteration)

        const __half* sA  = (const __half*)(smemraw + s * STG_BYTES);
        const __half* sBt = (const __half*)(smemraw + s * STG_BYTES + STG_B_OFF);
#pragma unroll
        for (int kk = 0; kk < GBK; kk += 16) {
            wmma::fragment<wmma::matrix_a, 16, 16, 16, __half, wmma::row_major> af[2];
            wmma::fragment<wmma::matrix_b, 16, 16, 16, __half, wmma::row_major> bf[4];
#pragma unroll
            for (int mi = 0; mi < 2; mi++)
                wmma::load_matrix_sync(af[mi], sA + (wm * 32 + mi * 16) * LDAh + kk, LDAh);
#pragma unroll
            for (int ni = 0; ni < 4; ni++)
                wmma::load_matrix_sync(bf[ni], sBt + kk * LDBh + wn * 64 + ni * 16, LDBh);
#pragma unroll
            for (int mi = 0; mi < 2; mi++)
#pragma unroll
                for (int ni = 0; ni < 4; ni++)
                    wmma::mma_sync(acc[mi][ni], af[mi], bf[ni], acc[mi][ni]);
        }

        // Prefetch tile t+2 into stage (t+2)%3
        const int tp = t + 2;
        if (tp < 32) {
            int sp = s + 2; if (sp >= 3) sp -= 3;
            uint32_t st = sb + sp * STG_BYTES;
#pragma unroll
            for (int i = 0; i < 2; i++) CP16(st + aoff[i], asrc[i] + tp * 32);
#pragma unroll
            for (int i = 0; i < 2; i++) CP16(st + boff[i], bsrc[i] + (size_t)tp * 32 * 1024);
        }
        CP_COMMIT();

        if (++s == 3) s = 0;
    }
    __syncthreads();   // protect smem scratch reuse below

    // Epilogue: per-warp 16x20 scratch roundtrip (f32), bias add,
    // half (internal QKV) or float (final y) vectorized stores.
    float* myC = (float*)smemraw + warp * 16 * 20;
    const int r  = lane >> 1;
    const int ch = (lane & 1) * 8;
    const bool outHalf = (w < 3);
#pragma unroll
    for (int mi = 0; mi < 2; mi++)
#pragma unroll
        for (int ni = 0; ni < 4; ni++) {
            wmma::store_matrix_sync(myC, acc[mi][ni], 20, wmma::mem_row_major);
            __syncwarp();
            int gm = bm * 128 + wm * 32 + mi * 16 + r;
            int gn = bn * 128 + wn * 64 + ni * 16 + ch;
            float c0 = myC[r * 20 + ch + 0] + bias[gn + 0];
            float c1 = myC[r * 20 + ch + 1] + bias[gn + 1];
            float c2 = myC[r * 20 + ch + 2] + bias[gn + 2];
            float c3 = myC[r * 20 + ch + 3] + bias[gn + 3];
            float c4 = myC[r * 20 + ch + 4] + bias[gn + 4];
            float c5 = myC[r * 20 + ch + 5] + bias[gn + 5];
            float c6 = myC[r * 20 + ch + 6] + bias[gn + 6];
            float c7 = myC[r * 20 + ch + 7] + bias[gn + 7];
            if (outHalf) {
                h2x4 pk;
                pk.a = __floats2half2_rn(c0, c1);
                pk.b = __floats2half2_rn(c2, c3);
                pk.c = __floats2half2_rn(c4, c5);
                pk.d = __floats2half2_rn(c6, c7);
                *(h2x4*)(Ch + (size_t)gm * 1024 + gn) = pk;
            } else {
                *(float4*)(Cext + (size_t)gm * 1024 + gn)     = make_float4(c0, c1, c2, c3);
                *(float4*)(Cext + (size_t)gm * 1024 + gn + 4) = make_float4(c4, c5, c6, c7);
            }
            __syncwarp();
        }
}

// ---------------------------------------------------------------------------
// Flash-style WMMA attention. One warp = one head, one block = 8 heads of a
// (batch, 16-query) tile; grid (BSZ, PP/16, 2). Per 16-wide j-chunk:
//   S[16x16] = Q·K^T via 4 wmma (Q frags cached, K col_major direct-global),
//   exp+window-mask in smem (one exp warp-instr covers 16 distinct scores —
//   vs 2 in the scalar kernel), P(half) -> a-frag, O += P·V via 4 wmma,
//   per-row l accumulated. Max-free softmax (scores bounded ~|3.3|).
// Out-of-range rows of the last chunk read the 16 zero-filled pad rows of
// g_k/g_v and are masked to weight 0. rel_err adds ~3e-4 from half P.
// ---------------------------------------------------------------------------
__global__ __launch_bounds__(256)
void attn_kernel()
{
    const int b    = blockIdx.x;
    const int tb   = blockIdx.y * ATQ;
    const int warp = threadIdx.x >> 5;
    const int lane = threadIdx.x & 31;
    const int h    = blockIdx.z * 8 + warp;

    __shared__ __align__(16) float  sS[8][16 * 16];
    __shared__ __align__(16) __half sP[8][16 * 16];
    __shared__ float sL[8][16];
    __shared__ float sInv[8][16];

    const __half* qb = g_q + ((size_t)b * PP + tb) * DWM + h * 64;
    const __half* kb = g_k + (size_t)b * PP * DWM + h * 64;
    const __half* vb = g_v + (size_t)b * PP * DWM + h * 64;

    int stv = 0;
    if (lane < ATQ) stv = g_start[b * PP + tb + lane];
    const int jmin = __shfl_sync(0xffffffffu, stv, 0);   // st monotone in t
    const int jmax = tb + ATQ - 1;

    const int row    = lane >> 1;          // 0..15 (query row)
    const int col0   = (lane & 1) * 8;     // 0 or 8
    const int st_row = __shfl_sync(0xffffffffu, stv, row);
    const int qg_row = tb + row;

    if (lane < 16) sL[warp][lane] = 0.0f;

    // Q fragments (row_major, ld = DWM), cached for all chunks
    wmma::fragment<wmma::matrix_a, 16, 16, 16, __half, wmma::row_major> aQ[4];
#pragma unroll
    for (int ks = 0; ks < 4; ks++)
        wmma::load_matrix_sync(aQ[ks], qb + ks * 16, DWM);

    wmma::fragment<wmma::accumulator, 16, 16, 16, float> accO[4];
#pragma unroll
    for (int ks = 0; ks < 4; ks++)
        wmma::fill_fragment(accO[ks], 0.0f);

    float*  Ss = sS[warp];
    __half* Ps = sP[warp];

    for (int jc = jmin; jc <= jmax; jc += 16) {
        // ---- S = Q · K^T over the 64-dim head ----
        wmma::fragment<wmma::accumulator, 16, 16, 16, float> accS;
        wmma::fill_fragment(accS, 0.0f);
#pragma unroll
        for (int ks = 0; ks < 4; ks++) {
            wmma::fragment<wmma::matrix_b, 16, 16, 16, __half, wmma::col_major> bK;
            wmma::load_matrix_sync(bK, kb + (size_t)jc * DWM + ks * 16, DWM);
            wmma::mma_sync(accS, aQ[ks], bK, accS);
        }
        wmma::store_matrix_sync(Ss, accS, 16, wmma::mem_row_major);
        __syncwarp();

        // ---- exp + window mask + row-sum partials + P(half) ----
        float lsum = 0.0f;
        __align__(16) __half hp[8];
#pragma unroll
        for (int c = 0; c < 8; c++) {
            int jg = jc + col0 + c;
            float sv = Ss[row * 16 + col0 + c];
            bool valid = (jg >= st_row) && (jg <= qg_row);
            float wt = valid ? __expf(sv * 0.125f) : 0.0f;
            lsum += wt;
            hp[c] = __float2half_rn(wt);
        }
        *(uint4*)&Ps[row * 16 + col0] = *(const uint4*)hp;
        lsum += __shfl_xor_sync(0xffffffffu, lsum, 1);
        if ((lane & 1) == 0) sL[warp][row] += lsum;   // one lane per row
        __syncwarp();

        // ---- O += P · V ----
        wmma::fragment<wmma::matrix_a, 16, 16, 16, __half, wmma::row_major> aP;
        wmma::load_matrix_sync(aP, Ps, 16);
#pragma unroll
        for (int ks = 0; ks < 4; ks++) {
            wmma::fragment<wmma::matrix_b, 16, 16, 16, __half, wmma::row_major> bV;
            wmma::load_matrix_sync(bV, vb + (size_t)jc * DWM + ks * 16, DWM);
            wmma::mma_sync(accO[ks], aP, bV, accO[ks]);
        }
        __syncwarp();   // all lanes done with Ss/Ps before next chunk rewrites
    }

    __syncwarp();
    if (lane < 16) sInv[warp][lane] = 1.0f / sL[warp][lane];
    __syncwarp();

    // ---- normalize + store (half, for the output projection GEMM) ----
    __half* ob = g_o + ((size_t)b * PP + tb) * DWM + h * 64;
    const float inv = sInv[warp][row];
#pragma unroll
    for (int ks = 0; ks < 4; ks++) {
        wmma::store_matrix_sync(Ss, accO[ks], 16, wmma::mem_row_major);
        __syncwarp();
        __align__(16) __half2 o2[4];
#pragma unroll
        for (int c = 0; c < 4; c++) {
            float x0 = Ss[row * 16 + col0 + 2 * c]     * inv;
            float x1 = Ss[row * 16 + col0 + 2 * c + 1] * inv;
            o2[c] = __floats2half2_rn(x0, x1);
        }
        *(h2x4*)(ob + (size_t)row * DWM + ks * 16 + col0) = *(const h2x4*)o2;
        __syncwarp();
    }
}

// ---------------------------------------------------------------------------
// Launch
// ---------------------------------------------------------------------------
extern "C" void kernel_launch(void* const* d_in, const int* in_sizes, int n_in,
                              void* d_out, int out_size)
{
    const float*         x  = (const float*)d_in[0];
    const unsigned char* rs = (const unsigned char*)d_in[1];
    const float* Wq = (const float*)d_in[2];
    const float* bq = (const float*)d_in[3];
    const float* Wk = (const float*)d_in[4];
    const float* bk = (const float*)d_in[5];
    const float* Wv = (const float*)d_in[6];
    const float* bv = (const float*)d_in[7];
    const float* Wo = (const float*)d_in[8];
    const float* bo = (const float*)d_in[9];
    float* y = (float*)d_out;

    cudaFuncSetAttribute(gemm_fp16_kernel,
                         cudaFuncAttributeMaxDynamicSharedMemorySize, GSMEM);

    prep_kernel<<<1, 256>>>(rs, bq, bk, bv, bo);
    conv_x_kernel<<<32768, 256>>>((const float4*)x);
    conv_w_kernel<<<dim3(1024, 4), 256>>>((const float4*)Wq, (const float4*)Wk,
                                          (const float4*)Wv, (const float4*)Wo);

    // Fused Q,K,V projections: grid.x = 3 weights * 8 bn, grid.y = 32768/128
    gemm_fp16_kernel<<<dim3(24, 256), 256, GSMEM>>>(nullptr, 0, 0);

    // Flash-style wmma attention: 8 heads/block, head halves on grid.z
    attn_kernel<<<dim3(BSZ, PP / ATQ, 2), 256>>>();

    // y = attn_out @ Wo + bo (f32 out)
    gemm_fp16_kernel<<<dim3(8, 256), 256, GSMEM>>>(y, 1, 3);
}